// round 5
// baseline (speedup 1.0000x reference)
#include <cuda_runtime.h>
#include <cuda_fp16.h>
#include <cstdint>

// ---------------------------------------------------------------------------
// ConstrainedEnhancementModel on GB300 (ptxas target sm_103: no 'a' features).
// R5: GEMM6 fp16 mma.sync + ldmatrix fragment loads, 64x64 warp tiles
// (4 warps / 128 threads per CTA, 2 CTAs/SM), 4-stage cp.async pipeline.
// transpose_cvt forked onto a side stream to overlap L1-L5.
// ---------------------------------------------------------------------------

#define NB   512
#define NL   256
#define NF   32
#define NH   4096
#define NOUTCOL (NH * NF)          // 131072
#define LAST_KNOT ((NL - 1) * 16)  // 4080

// Scratch (device globals; allocation-free rule)
__device__ float  g_h1[512 * 1024];
__device__ float  g_h2[512 * 512];
__device__ float  g_fe[512 * 256];
__device__ float  g_d1[512 * 512];
__device__ __half g_d2h[512 * 1024];
__device__ __half g_w6t[(size_t)NOUTCOL * 1024];   // 256 MB, [n][k] fp16

// ===========================================================================
// helpers
// ===========================================================================
__device__ __forceinline__ uint32_t smem_u32(const void* p) {
    uint32_t a;
    asm("{ .reg .u64 t; cvta.to.shared.u64 t, %1; cvt.u32.u64 %0, t; }"
        : "=r"(a) : "l"(p));
    return a;
}
__device__ __forceinline__ void cp16_ca(uint32_t dst, const void* src) {
    asm volatile("cp.async.ca.shared.global [%0], [%1], 16;"
                 :: "r"(dst), "l"(src) : "memory");
}
__device__ __forceinline__ void cp16_cg(uint32_t dst, const void* src) {
    asm volatile("cp.async.cg.shared.global [%0], [%1], 16;"
                 :: "r"(dst), "l"(src) : "memory");
}
#define CP_COMMIT() asm volatile("cp.async.commit_group;" ::: "memory")
#define CP_WAIT2()  asm volatile("cp.async.wait_group 2;" ::: "memory")

__device__ __forceinline__ void ldsm_x4(uint32_t& r0, uint32_t& r1,
                                        uint32_t& r2, uint32_t& r3, uint32_t addr) {
    asm volatile("ldmatrix.sync.aligned.m8n8.x4.shared.b16 {%0,%1,%2,%3}, [%4];"
                 : "=r"(r0), "=r"(r1), "=r"(r2), "=r"(r3) : "r"(addr));
}

__device__ __forceinline__ void mma_fp16(float& c0, float& c1, float& c2, float& c3,
                                         uint32_t a0, uint32_t a1, uint32_t a2, uint32_t a3,
                                         uint32_t b0, uint32_t b1) {
    asm volatile(
        "mma.sync.aligned.m16n8k16.row.col.f32.f16.f16.f32 "
        "{%0,%1,%2,%3}, {%4,%5,%6,%7}, {%8,%9}, {%0,%1,%2,%3};"
        : "+f"(c0), "+f"(c1), "+f"(c2), "+f"(c3)
        : "r"(a0), "r"(a1), "r"(a2), "r"(a3), "r"(b0), "r"(b1));
}

// ===========================================================================
// transpose + convert: w6 fp32 [1024][131072] -> g_w6t fp16 [131072][1024]
// ===========================================================================
__global__ void __launch_bounds__(256)
transpose_cvt(const float* __restrict__ in, __half* __restrict__ outp)
{
    __shared__ float ts[32][33];
    const int tx = threadIdx.x & 31;
    const int ty = threadIdx.x >> 5;
    const int n0 = blockIdx.x * 32;
    const int k0 = blockIdx.y * 32;

#pragma unroll
    for (int i = 0; i < 4; i++)
        ts[ty + 8 * i][tx] = in[(size_t)(k0 + ty + 8 * i) * NOUTCOL + n0 + tx];
    __syncthreads();
#pragma unroll
    for (int i = 0; i < 4; i++)
        outp[(size_t)(n0 + ty + 8 * i) * 1024 + k0 + tx] =
            __float2half(ts[tx][ty + 8 * i]);
}

// ===========================================================================
// GEMM6 fp16: out = epilogue( d2h(512x1024) @ w6t^T + b6 )
// CTA 128x128, 4 warps (2M x 2N), warp tile 64x64, K-step 16, 4-stage cp.async.
// ldmatrix.x4 fragment loads; SMEM pitch 24 halfs (48B rows) -> all ldmatrix
// phases and cp.async stores conflict-light / reads conflict-free.
// ===========================================================================
#define G6_STG    4
#define G6_PITCH  24                       // halfs per row (16 data + 8 pad)
#define G6_TILEH  (128 * G6_PITCH)         // 3072 halfs per stage
#define G6_TILEB  (G6_TILEH * 2)           // 6144 bytes per stage
#define G6_NKT    64                       // 1024 / 16
#define G6_SMEMB  (8 * G6_TILEB + 512)     // A(4) + B(4) stages + bias

__global__ void __launch_bounds__(128, 2)
gemm6_fp16(const __half* __restrict__ Ah,   // d2h: 512 x 1024
           const __half* __restrict__ Bt,   // w6t: 131072 x 1024
           const float* __restrict__ bias,  // b6
           const float* __restrict__ low,   // 512 x 256 x 32
           float* __restrict__ out)         // 512 x 4096 x 32
{
    extern __shared__ __half sm[];
    __half* Asm = sm;                        // 4 stages
    __half* Bsm = sm + 4 * G6_TILEH;         // 4 stages
    float*  sbias = reinterpret_cast<float*>(sm + 8 * G6_TILEH);

    const int tid  = threadIdx.x;
    const int wid  = tid >> 5;      // 0..3
    const int lane = tid & 31;
    const int g    = lane >> 2;     // 0..7
    const int q    = lane & 3;      // 0..3

    const int bm = blockIdx.x * 128;   // 4 M-blocks fastest -> share w6 in L2
    const int bn = blockIdx.y * 128;

    const int wm = (wid >> 1) * 64;
    const int wn = (wid & 1) * 64;

    sbias[tid] = bias[bn + tid];

    // cp.async: each thread owns one row (tid) of both tiles, 2 chunks each
    const __half* aSrc = Ah + (size_t)(bm + tid) * 1024;
    const __half* bSrc = Bt + (size_t)(bn + tid) * 1024;
    const uint32_t aBase = smem_u32(Asm);
    const uint32_t bBase = smem_u32(Bsm);
    const uint32_t aDst = aBase + tid * 48;
    const uint32_t bDst = bBase + tid * 48;

#define G6_LOAD(s, kt)                                              \
    do {                                                            \
        cp16_ca(aDst + (s) * G6_TILEB,      aSrc + (kt) * 16);      \
        cp16_ca(aDst + (s) * G6_TILEB + 16, aSrc + (kt) * 16 + 8);  \
        cp16_cg(bDst + (s) * G6_TILEB,      bSrc + (kt) * 16);      \
        cp16_cg(bDst + (s) * G6_TILEB + 16, bSrc + (kt) * 16 + 8);  \
    } while (0)

    G6_LOAD(0, 0); CP_COMMIT();
    G6_LOAD(1, 1); CP_COMMIT();
    G6_LOAD(2, 2); CP_COMMIT();

    // ldmatrix per-thread base addresses
    const int mi = lane >> 3;      // matrix slot 0..3
    const int r8 = lane & 7;
    // A: matrices (rows +0/+8) x (k 0/8):  slot -> (mi&1)*8 rows, (mi>>1)*8 k
    const uint32_t aLd = aBase +
        (uint32_t)(((wm + (mi & 1) * 8 + r8) * G6_PITCH + (mi >> 1) * 8) * 2);
    // B: matrices (n +0/+8) x (k 0/8): slot -> (mi>>1)*8 rows, (mi&1)*8 k
    const uint32_t bLd = bBase +
        (uint32_t)(((wn + (mi >> 1) * 8 + r8) * G6_PITCH + (mi & 1) * 8) * 2);

    float acc[4][8][4];
#pragma unroll
    for (int i = 0; i < 4; i++)
#pragma unroll
        for (int j = 0; j < 8; j++)
#pragma unroll
            for (int k = 0; k < 4; k++) acc[i][j][k] = 0.0f;

    for (int kt = 0; kt < G6_NKT; kt++) {
        const int s = kt & (G6_STG - 1);
        CP_WAIT2();
        __syncthreads();
        if (kt + 3 < G6_NKT) {
            G6_LOAD((kt + 3) & (G6_STG - 1), kt + 3);
        }
        CP_COMMIT();

        const uint32_t so = (uint32_t)s * G6_TILEB;

        uint32_t bf[8][2];
#pragma unroll
        for (int p = 0; p < 4; p++)   // 16 n-rows per ldmatrix.x4
            ldsm_x4(bf[2 * p][0], bf[2 * p][1],
                    bf[2 * p + 1][0], bf[2 * p + 1][1],
                    bLd + p * (16 * G6_PITCH * 2) + so);

#pragma unroll
        for (int mt = 0; mt < 4; mt++) {
            uint32_t a0, a1, a2, a3;
            ldsm_x4(a0, a1, a2, a3, aLd + mt * (16 * G6_PITCH * 2) + so);
#pragma unroll
            for (int nt = 0; nt < 8; nt++)
                mma_fp16(acc[mt][nt][0], acc[mt][nt][1],
                         acc[mt][nt][2], acc[mt][nt][3],
                         a0, a1, a2, a3, bf[nt][0], bf[nt][1]);
        }
    }

    // ---- fused epilogue ----
#pragma unroll
    for (int mt = 0; mt < 4; mt++) {
#pragma unroll
        for (int h = 0; h < 2; h++) {
            const int r = bm + wm + mt * 16 + g + h * 8;
            const float* lowr = low + (size_t)r * (NL * NF);
            float* outr = out + (size_t)r * NOUTCOL;
#pragma unroll
            for (int nt = 0; nt < 8; nt++) {
                const int colb = wn + nt * 8;          // 0..120, mult of 8
                const int t    = (bn + colb) >> 5;
                const int rem  = t & 15;
                const int seg  = t >> 4;
                const bool knot  = (rem == 0);
                const bool inseg = (!knot) && (t < LAST_KNOT);
                const float alpha = (float)rem * 0.0625f;
                const int segB = (seg < NL - 1) ? seg + 1 : NL - 1;
                const int f = (colb & 31) + 2 * q;

                float dec0 = acc[mt][nt][2 * h]     + sbias[colb + 2 * q];
                float dec1 = acc[mt][nt][2 * h + 1] + sbias[colb + 2 * q + 1];
                float2 la = *reinterpret_cast<const float2*>(lowr + seg  * NF + f);
                float2 lb = *reinterpret_cast<const float2*>(lowr + segB * NF + f);
                float lin0 = (1.0f - alpha) * la.x + alpha * lb.x;
                float lin1 = (1.0f - alpha) * la.y + alpha * lb.y;
                float r0 = knot ? la.x : (inseg ? 0.8f * lin0 + 0.2f * dec0 : dec0);
                float r1 = knot ? la.y : (inseg ? 0.8f * lin1 + 0.2f * dec1 : dec1);
                *reinterpret_cast<float2*>(outr + bn + colb + 2 * q) =
                    make_float2(r0, r1);
            }
        }
    }
#undef G6_LOAD
}

// ===========================================================================
// Small-layer SIMT SGEMM, templated output type (fp32 or fp16 store)
// ===========================================================================
__device__ __forceinline__ void store4(float* p, float4 v) {
    *reinterpret_cast<float4*>(p) = v;
}
__device__ __forceinline__ void store4(__half* p, float4 v) {
    __half2 h0 = __floats2half2_rn(v.x, v.y);
    __half2 h1 = __floats2half2_rn(v.z, v.w);
    *reinterpret_cast<__half2*>(p)     = h0;
    *reinterpret_cast<__half2*>(p + 2) = h1;
}

template <int BM, int BN, int BK, int TM, int TN, bool RELU, typename OutT>
__global__ __launch_bounds__((BM / TM) * (BN / TN))
void sgemm_bias(const float* __restrict__ A, const float* __restrict__ Bm,
                const float* __restrict__ bias, OutT* __restrict__ C,
                int M, int N, int K)
{
    constexpr int THREADS = (BM / TM) * (BN / TN);
    __shared__ float As[BK][BM + 4];
    __shared__ float Bs[BK][BN];

    const int tid = threadIdx.x;
    const int bn  = blockIdx.x * BN;
    const int bm  = blockIdx.y * BM;
    const int tx  = tid % (BN / TN);
    const int ty  = tid / (BN / TN);

    float acc[TM][TN];
#pragma unroll
    for (int i = 0; i < TM; i++)
#pragma unroll
        for (int j = 0; j < TN; j++) acc[i][j] = 0.0f;

    constexpr int AV = BK / 4;
    constexpr int AT = BM * AV;
    constexpr int BV = BN / 4;
    constexpr int BT = BK * BV;

    for (int k0 = 0; k0 < K; k0 += BK) {
        for (int i = tid; i < AT; i += THREADS) {
            int r  = i / AV;
            int c4 = (i % AV) * 4;
            float4 v = *reinterpret_cast<const float4*>(
                A + (size_t)(bm + r) * K + k0 + c4);
            As[c4 + 0][r] = v.x;
            As[c4 + 1][r] = v.y;
            As[c4 + 2][r] = v.z;
            As[c4 + 3][r] = v.w;
        }
        for (int i = tid; i < BT; i += THREADS) {
            int r  = i / BV;
            int c4 = (i % BV) * 4;
            *reinterpret_cast<float4*>(&Bs[r][c4]) =
                *reinterpret_cast<const float4*>(
                    Bm + (size_t)(k0 + r) * N + bn + c4);
        }
        __syncthreads();

#pragma unroll
        for (int kk = 0; kk < BK; kk++) {
            float ra[TM], rb[TN];
#pragma unroll
            for (int i = 0; i < TM; i += 4)
                *reinterpret_cast<float4*>(&ra[i]) =
                    *reinterpret_cast<const float4*>(&As[kk][ty * TM + i]);
#pragma unroll
            for (int j = 0; j < TN; j += 4)
                *reinterpret_cast<float4*>(&rb[j]) =
                    *reinterpret_cast<const float4*>(&Bs[kk][tx * TN + j]);
#pragma unroll
            for (int i = 0; i < TM; i++)
#pragma unroll
                for (int j = 0; j < TN; j++)
                    acc[i][j] = fmaf(ra[i], rb[j], acc[i][j]);
        }
        __syncthreads();
    }

#pragma unroll
    for (int i = 0; i < TM; i++) {
        int row = bm + ty * TM + i;
#pragma unroll
        for (int j = 0; j < TN; j += 4) {
            int col = bn + tx * TN + j;
            float4 v;
            v.x = acc[i][j + 0] + bias[col + 0];
            v.y = acc[i][j + 1] + bias[col + 1];
            v.z = acc[i][j + 2] + bias[col + 2];
            v.w = acc[i][j + 3] + bias[col + 3];
            if (RELU) {
                v.x = fmaxf(v.x, 0.0f);
                v.y = fmaxf(v.y, 0.0f);
                v.z = fmaxf(v.z, 0.0f);
                v.w = fmaxf(v.w, 0.0f);
            }
            store4(C + (size_t)row * N + col, v);
        }
    }
}

// ---------------------------------------------------------------------------
extern "C" void kernel_launch(void* const* d_in, const int* in_sizes, int n_in,
                              void* d_out, int out_size)
{
    const float* low = (const float*)d_in[0];
    const float* w1  = (const float*)d_in[1];
    const float* b1  = (const float*)d_in[2];
    const float* w2  = (const float*)d_in[3];
    const float* b2  = (const float*)d_in[4];
    const float* w3  = (const float*)d_in[5];
    const float* b3  = (const float*)d_in[6];
    const float* w4  = (const float*)d_in[7];
    const float* b4  = (const float*)d_in[8];
    const float* w5  = (const float*)d_in[9];
    const float* b5  = (const float*)d_in[10];
    const float* w6  = (const float*)d_in[11];
    const float* b6  = (const float*)d_in[12];
    float* out = (float*)d_out;

    float  *h1, *h2, *fe, *d1;
    __half *d2h, *w6t;
    cudaGetSymbolAddress((void**)&h1,  g_h1);
    cudaGetSymbolAddress((void**)&h2,  g_h2);
    cudaGetSymbolAddress((void**)&fe,  g_fe);
    cudaGetSymbolAddress((void**)&d1,  g_d1);
    cudaGetSymbolAddress((void**)&d2h, g_d2h);
    cudaGetSymbolAddress((void**)&w6t, g_w6t);

    cudaFuncSetAttribute(gemm6_fp16,
                         cudaFuncAttributeMaxDynamicSharedMemorySize, G6_SMEMB);

    static cudaStream_t s_side = nullptr;
    static cudaEvent_t ev_fork = nullptr, ev_join = nullptr;
    if (s_side == nullptr) {
        cudaStreamCreateWithFlags(&s_side, cudaStreamNonBlocking);
        cudaEventCreateWithFlags(&ev_fork, cudaEventDisableTiming);
        cudaEventCreateWithFlags(&ev_join, cudaEventDisableTiming);
    }

    // Fork: w6 transpose/convert runs alongside L1-L5
    cudaEventRecord(ev_fork, 0);
    cudaStreamWaitEvent(s_side, ev_fork, 0);
    transpose_cvt<<<dim3(NOUTCOL / 32, 1024 / 32), 256, 0, s_side>>>(w6, w6t);
    cudaEventRecord(ev_join, s_side);

    // L1: (512x8192)@(8192x1024) + relu
    sgemm_bias<64, 64, 16, 4, 4, true, float>
        <<<dim3(1024 / 64, 512 / 64), 256>>>(low, w1, b1, h1, 512, 1024, 8192);
    // L2: (512x1024)@(1024x512) + relu
    sgemm_bias<64, 64, 16, 4, 4, true, float>
        <<<dim3(512 / 64, 512 / 64), 256>>>(h1, w2, b2, h2, 512, 512, 1024);
    // L3: (512x512)@(512x256)
    sgemm_bias<64, 64, 16, 4, 4, false, float>
        <<<dim3(256 / 64, 512 / 64), 256>>>(h2, w3, b3, fe, 512, 256, 512);
    // L4: (512x256)@(256x512) + relu
    sgemm_bias<64, 64, 16, 4, 4, true, float>
        <<<dim3(512 / 64, 512 / 64), 256>>>(fe, w4, b4, d1, 512, 512, 256);
    // L5: (512x512)@(512x1024) + relu, fp16 output
    sgemm_bias<64, 64, 16, 4, 4, true, __half>
        <<<dim3(1024 / 64, 512 / 64), 256>>>(d1, w5, b5, d2h, 512, 1024, 512);

    // Join, then L6
    cudaStreamWaitEvent(0, ev_join, 0);
    gemm6_fp16<<<dim3(4, NOUTCOL / 128), 128, G6_SMEMB>>>(d2h, w6t, b6, low, out);
}

// round 6
// speedup vs baseline: 1.1072x; 1.1072x over previous
#include <cuda_runtime.h>
#include <cuda_fp16.h>
#include <cstdint>

// ---------------------------------------------------------------------------
// ConstrainedEnhancementModel on GB300 (ptxas target sm_103: no 'a' features).
// R6: GEMM6 fp16 mma.sync + ldmatrix, operands PRE-PACKED tile-major so every
// cp.async stage load is one contiguous 4KB block (fixes L1tex wavefront
// bottleneck found in R4/R5). 256 thr/CTA, 64x32 warp tiles, 2 CTAs/SM.
// pack_w6 forked to overlap L1-L5.
// ---------------------------------------------------------------------------

#define NB   512
#define NL   256
#define NF   32
#define NH   4096
#define NOUTCOL (NH * NF)          // 131072
#define LAST_KNOT ((NL - 1) * 16)  // 4080

// Scratch (device globals; allocation-free rule)
__device__ float  g_h1[512 * 1024];
__device__ float  g_h2[512 * 512];
__device__ float  g_fe[512 * 256];
__device__ float  g_d1[512 * 512];
__device__ __half g_d2h[512 * 1024];                // tiled [kt][m][16]
__device__ __half g_w6t[(size_t)NOUTCOL * 1024];    // tiled [nblk][kt][128][16]

// ===========================================================================
// helpers
// ===========================================================================
__device__ __forceinline__ uint32_t smem_u32(const void* p) {
    uint32_t a;
    asm("{ .reg .u64 t; cvta.to.shared.u64 t, %1; cvt.u32.u64 %0, t; }"
        : "=r"(a) : "l"(p));
    return a;
}
__device__ __forceinline__ void cp16_ca(uint32_t dst, const void* src) {
    asm volatile("cp.async.ca.shared.global [%0], [%1], 16;"
                 :: "r"(dst), "l"(src) : "memory");
}
__device__ __forceinline__ void cp16_cg(uint32_t dst, const void* src) {
    asm volatile("cp.async.cg.shared.global [%0], [%1], 16;"
                 :: "r"(dst), "l"(src) : "memory");
}
#define CP_COMMIT() asm volatile("cp.async.commit_group;" ::: "memory")
#define CP_WAIT2()  asm volatile("cp.async.wait_group 2;" ::: "memory")

__device__ __forceinline__ void ldsm_x4(uint32_t& r0, uint32_t& r1,
                                        uint32_t& r2, uint32_t& r3, uint32_t addr) {
    asm volatile("ldmatrix.sync.aligned.m8n8.x4.shared.b16 {%0,%1,%2,%3}, [%4];"
                 : "=r"(r0), "=r"(r1), "=r"(r2), "=r"(r3) : "r"(addr));
}

__device__ __forceinline__ void mma_fp16(float& c0, float& c1, float& c2, float& c3,
                                         uint32_t a0, uint32_t a1, uint32_t a2, uint32_t a3,
                                         uint32_t b0, uint32_t b1) {
    asm volatile(
        "mma.sync.aligned.m16n8k16.row.col.f32.f16.f16.f32 "
        "{%0,%1,%2,%3}, {%4,%5,%6,%7}, {%8,%9}, {%0,%1,%2,%3};"
        : "+f"(c0), "+f"(c1), "+f"(c2), "+f"(c3)
        : "r"(a0), "r"(a1), "r"(a2), "r"(a3), "r"(b0), "r"(b1));
}

// ===========================================================================
// pack_w6: w6 fp32 [1024 k][131072 n] -> fp16 tile-major
//          g_w6t[nblk][kt][n128][k16], each (nblk,kt) tile contiguous 4KB.
// grid (1024 nblk, 64 kt), 256 threads.
// ===========================================================================
__global__ void __launch_bounds__(256)
pack_w6(const float* __restrict__ in, __half* __restrict__ outp)
{
    __shared__ __half ts[16][136];
    const int tid = threadIdx.x;
    const int blk = blockIdx.x;
    const int kt  = blockIdx.y;

    // read 16 k-rows x 128 n (coalesced)
#pragma unroll
    for (int i = tid; i < 2048; i += 256) {
        const int k = i >> 7, n = i & 127;
        ts[k][n] = __float2half(
            in[(size_t)(kt * 16 + k) * NOUTCOL + blk * 128 + n]);
    }
    __syncthreads();

    // write [n][k]: thread -> n = tid>>1, k-half = (tid&1)*8 (16B contiguous)
    const int n  = tid >> 1;
    const int kh = (tid & 1) * 8;
    __half tmp[8];
#pragma unroll
    for (int j = 0; j < 8; j++) tmp[j] = ts[kh + j][n];
    __half* dst = outp + ((size_t)(blk * 64 + kt) * 128 + n) * 16 + kh;
    *reinterpret_cast<uint4*>(dst) = *reinterpret_cast<const uint4*>(tmp);
}

// ===========================================================================
// GEMM6 fp16: out = epilogue( d2h @ w6t^T + b6 )
// CTA 128x128, 8 warps (2M x 4N), warp tile 64x32, K-step 16,
// 4-stage cp.async (every stage load = contiguous 4KB), ldmatrix.x4 frags.
// SMEM pitch 24 halfs (48B rows) -> ldmatrix phases conflict-free.
// ===========================================================================
#define G6_STG    4
#define G6_PITCH  24                       // halfs per row (16 data + 8 pad)
#define G6_TILEH  (128 * G6_PITCH)         // 3072 halfs per stage
#define G6_TILEB  (G6_TILEH * 2)           // 6144 bytes per stage
#define G6_NKT    64                       // 1024 / 16
#define G6_SMEMB  (8 * G6_TILEB + 512)     // A(4)+B(4) stages + bias

__global__ void __launch_bounds__(256, 2)
gemm6_fp16(const __half* __restrict__ Ah,   // d2h tiled [64][512][16]
           const __half* __restrict__ Bt,   // w6t tiled [1024][64][128][16]
           const float* __restrict__ bias,  // b6
           const float* __restrict__ low,   // 512 x 256 x 32
           float* __restrict__ out)         // 512 x 4096 x 32
{
    extern __shared__ __half sm[];
    __half* Asm = sm;                        // 4 stages
    __half* Bsm = sm + 4 * G6_TILEH;         // 4 stages
    float*  sbias = reinterpret_cast<float*>(sm + 8 * G6_TILEH);

    const int tid  = threadIdx.x;
    const int wid  = tid >> 5;      // 0..7
    const int lane = tid & 31;
    const int g    = lane >> 2;     // 0..7
    const int q    = lane & 3;      // 0..3

    const int bm = blockIdx.x * 128;   // 4 M-blocks fastest -> share w6 in L2
    const int bn = blockIdx.y * 128;

    const int wm = (wid >> 2) * 64;    // 0/64
    const int wn = (wid & 3) * 32;     // 0..96

    if (tid < 128) sbias[tid] = bias[bn + tid];

    // cp.async: contiguous 4KB per stage per operand (256 thr x 16B)
    const __half* aSrc = Ah + (size_t)bm * 16 + tid * 8;          // +8192/kt
    const __half* bSrc = Bt + (size_t)blockIdx.y * 64 * 2048 + tid * 8; // +2048/kt
    const uint32_t aBase = smem_u32(Asm);
    const uint32_t bBase = smem_u32(Bsm);
    const uint32_t aDst = aBase + (tid >> 1) * 48 + (tid & 1) * 16;
    const uint32_t bDst = bBase + (tid >> 1) * 48 + (tid & 1) * 16;

#define G6_LOAD(s, kt)                                         \
    do {                                                       \
        cp16_ca(aDst + (s) * G6_TILEB, aSrc + (kt) * 8192);    \
        cp16_cg(bDst + (s) * G6_TILEB, bSrc + (kt) * 2048);    \
    } while (0)

    G6_LOAD(0, 0); CP_COMMIT();
    G6_LOAD(1, 1); CP_COMMIT();
    G6_LOAD(2, 2); CP_COMMIT();

    // ldmatrix per-thread base addresses (mapping validated in R5)
    const int mi = lane >> 3;      // matrix slot 0..3
    const int r8 = lane & 7;
    // A slots: rows +(mi&1)*8, k +(mi>>1)*8  -> r0..r3 = (m0k0,m8k0,m0k8,m8k8)
    const uint32_t aLd = aBase +
        (uint32_t)(((wm + (mi & 1) * 8 + r8) * G6_PITCH + (mi >> 1) * 8) * 2);
    // B slots: n +(mi>>1)*8, k +(mi&1)*8     -> r0..r3 = (n0k0,n0k8,n8k0,n8k8)
    const uint32_t bLd = bBase +
        (uint32_t)(((wn + (mi >> 1) * 8 + r8) * G6_PITCH + (mi & 1) * 8) * 2);

    float acc[4][4][4];
#pragma unroll
    for (int i = 0; i < 4; i++)
#pragma unroll
        for (int j = 0; j < 4; j++)
#pragma unroll
            for (int k = 0; k < 4; k++) acc[i][j][k] = 0.0f;

    for (int kt = 0; kt < G6_NKT; kt++) {
        const int s = kt & (G6_STG - 1);
        CP_WAIT2();
        __syncthreads();
        if (kt + 3 < G6_NKT) {
            G6_LOAD((kt + 3) & (G6_STG - 1), kt + 3);
        }
        CP_COMMIT();

        const uint32_t so = (uint32_t)s * G6_TILEB;

        uint32_t bf[4][2];
#pragma unroll
        for (int p = 0; p < 2; p++)    // 16 n-rows per ldsm.x4
            ldsm_x4(bf[2 * p][0], bf[2 * p][1],
                    bf[2 * p + 1][0], bf[2 * p + 1][1],
                    bLd + p * (16 * G6_PITCH * 2) + so);

#pragma unroll
        for (int mt = 0; mt < 4; mt++) {
            uint32_t a0, a1, a2, a3;
            ldsm_x4(a0, a1, a2, a3, aLd + mt * (16 * G6_PITCH * 2) + so);
#pragma unroll
            for (int nt = 0; nt < 4; nt++)
                mma_fp16(acc[mt][nt][0], acc[mt][nt][1],
                         acc[mt][nt][2], acc[mt][nt][3],
                         a0, a1, a2, a3, bf[nt][0], bf[nt][1]);
        }
    }

    // ---- fused epilogue (warp-uniform t) ----
    const int t   = (bn + wn) >> 5;
    const int rem = t & 15;
    const int seg = t >> 4;
    const bool knot  = (rem == 0);
    const bool inseg = (!knot) && (t < LAST_KNOT);
    const float alpha = (float)rem * 0.0625f;
    const int segB = (seg < NL - 1) ? seg + 1 : NL - 1;

#pragma unroll
    for (int mt = 0; mt < 4; mt++) {
#pragma unroll
        for (int h = 0; h < 2; h++) {
            const int r = bm + wm + mt * 16 + g + h * 8;
            const float* lowr = low + (size_t)r * (NL * NF);
            float* outr = out + (size_t)r * NOUTCOL + bn + wn;
#pragma unroll
            for (int nt = 0; nt < 4; nt++) {
                const int f = nt * 8 + 2 * q;
                float dec0 = acc[mt][nt][2 * h]     + sbias[wn + f];
                float dec1 = acc[mt][nt][2 * h + 1] + sbias[wn + f + 1];
                float2 la = *reinterpret_cast<const float2*>(lowr + seg  * NF + f);
                float2 lb = *reinterpret_cast<const float2*>(lowr + segB * NF + f);
                float lin0 = (1.0f - alpha) * la.x + alpha * lb.x;
                float lin1 = (1.0f - alpha) * la.y + alpha * lb.y;
                float r0 = knot ? la.x : (inseg ? 0.8f * lin0 + 0.2f * dec0 : dec0);
                float r1 = knot ? la.y : (inseg ? 0.8f * lin1 + 0.2f * dec1 : dec1);
                *reinterpret_cast<float2*>(outr + f) = make_float2(r0, r1);
            }
        }
    }
#undef G6_LOAD
}

// ===========================================================================
// Small-layer SIMT SGEMM; OutT float = plain store, TILED -> fp16 k-tiled
// layout [col/16][row][16] for GEMM6 A operand.
// ===========================================================================
template <int BM, int BN, int BK, int TM, int TN, bool RELU, bool TILEDH>
__global__ __launch_bounds__((BM / TM) * (BN / TN))
void sgemm_bias(const float* __restrict__ A, const float* __restrict__ Bm,
                const float* __restrict__ bias, void* __restrict__ Cv,
                int M, int N, int K)
{
    constexpr int THREADS = (BM / TM) * (BN / TN);
    __shared__ float As[BK][BM + 4];
    __shared__ float Bs[BK][BN];

    const int tid = threadIdx.x;
    const int bn  = blockIdx.x * BN;
    const int bm  = blockIdx.y * BM;
    const int tx  = tid % (BN / TN);
    const int ty  = tid / (BN / TN);

    float acc[TM][TN];
#pragma unroll
    for (int i = 0; i < TM; i++)
#pragma unroll
        for (int j = 0; j < TN; j++) acc[i][j] = 0.0f;

    constexpr int AV = BK / 4;
    constexpr int AT = BM * AV;
    constexpr int BV = BN / 4;
    constexpr int BT = BK * BV;

    for (int k0 = 0; k0 < K; k0 += BK) {
        for (int i = tid; i < AT; i += THREADS) {
            int r  = i / AV;
            int c4 = (i % AV) * 4;
            float4 v = *reinterpret_cast<const float4*>(
                A + (size_t)(bm + r) * K + k0 + c4);
            As[c4 + 0][r] = v.x;
            As[c4 + 1][r] = v.y;
            As[c4 + 2][r] = v.z;
            As[c4 + 3][r] = v.w;
        }
        for (int i = tid; i < BT; i += THREADS) {
            int r  = i / BV;
            int c4 = (i % BV) * 4;
            *reinterpret_cast<float4*>(&Bs[r][c4]) =
                *reinterpret_cast<const float4*>(
                    Bm + (size_t)(k0 + r) * N + bn + c4);
        }
        __syncthreads();

#pragma unroll
        for (int kk = 0; kk < BK; kk++) {
            float ra[TM], rb[TN];
#pragma unroll
            for (int i = 0; i < TM; i += 4)
                *reinterpret_cast<float4*>(&ra[i]) =
                    *reinterpret_cast<const float4*>(&As[kk][ty * TM + i]);
#pragma unroll
            for (int j = 0; j < TN; j += 4)
                *reinterpret_cast<float4*>(&rb[j]) =
                    *reinterpret_cast<const float4*>(&Bs[kk][tx * TN + j]);
#pragma unroll
            for (int i = 0; i < TM; i++)
#pragma unroll
                for (int j = 0; j < TN; j++)
                    acc[i][j] = fmaf(ra[i], rb[j], acc[i][j]);
        }
        __syncthreads();
    }

#pragma unroll
    for (int i = 0; i < TM; i++) {
        int row = bm + ty * TM + i;
#pragma unroll
        for (int j = 0; j < TN; j += 4) {
            int col = bn + tx * TN + j;
            float4 v;
            v.x = acc[i][j + 0] + bias[col + 0];
            v.y = acc[i][j + 1] + bias[col + 1];
            v.z = acc[i][j + 2] + bias[col + 2];
            v.w = acc[i][j + 3] + bias[col + 3];
            if (RELU) {
                v.x = fmaxf(v.x, 0.0f);
                v.y = fmaxf(v.y, 0.0f);
                v.z = fmaxf(v.z, 0.0f);
                v.w = fmaxf(v.w, 0.0f);
            }
            if (TILEDH) {
                // tiled half layout: [col/16][row][16]
                __half* C = (__half*)Cv;
                __half* p = C + ((size_t)(col >> 4) * M + row) * 16 + (col & 15);
                __half2 h0 = __floats2half2_rn(v.x, v.y);
                __half2 h1 = __floats2half2_rn(v.z, v.w);
                *reinterpret_cast<__half2*>(p)     = h0;
                *reinterpret_cast<__half2*>(p + 2) = h1;
            } else {
                float* C = (float*)Cv;
                *reinterpret_cast<float4*>(C + (size_t)row * N + col) = v;
            }
        }
    }
}

// ---------------------------------------------------------------------------
extern "C" void kernel_launch(void* const* d_in, const int* in_sizes, int n_in,
                              void* d_out, int out_size)
{
    const float* low = (const float*)d_in[0];
    const float* w1  = (const float*)d_in[1];
    const float* b1  = (const float*)d_in[2];
    const float* w2  = (const float*)d_in[3];
    const float* b2  = (const float*)d_in[4];
    const float* w3  = (const float*)d_in[5];
    const float* b3  = (const float*)d_in[6];
    const float* w4  = (const float*)d_in[7];
    const float* b4  = (const float*)d_in[8];
    const float* w5  = (const float*)d_in[9];
    const float* b5  = (const float*)d_in[10];
    const float* w6  = (const float*)d_in[11];
    const float* b6  = (const float*)d_in[12];
    float* out = (float*)d_out;

    float  *h1, *h2, *fe, *d1;
    __half *d2h, *w6t;
    cudaGetSymbolAddress((void**)&h1,  g_h1);
    cudaGetSymbolAddress((void**)&h2,  g_h2);
    cudaGetSymbolAddress((void**)&fe,  g_fe);
    cudaGetSymbolAddress((void**)&d1,  g_d1);
    cudaGetSymbolAddress((void**)&d2h, g_d2h);
    cudaGetSymbolAddress((void**)&w6t, g_w6t);

    cudaFuncSetAttribute(gemm6_fp16,
                         cudaFuncAttributeMaxDynamicSharedMemorySize, G6_SMEMB);

    static cudaStream_t s_side = nullptr;
    static cudaEvent_t ev_fork = nullptr, ev_join = nullptr;
    if (s_side == nullptr) {
        cudaStreamCreateWithFlags(&s_side, cudaStreamNonBlocking);
        cudaEventCreateWithFlags(&ev_fork, cudaEventDisableTiming);
        cudaEventCreateWithFlags(&ev_join, cudaEventDisableTiming);
    }

    // Fork: w6 pack runs alongside L1-L5
    cudaEventRecord(ev_fork, 0);
    cudaStreamWaitEvent(s_side, ev_fork, 0);
    pack_w6<<<dim3(NOUTCOL / 128, 64), 256, 0, s_side>>>(w6, w6t);
    cudaEventRecord(ev_join, s_side);

    // L1: (512x8192)@(8192x1024) + relu
    sgemm_bias<64, 64, 16, 4, 4, true, false>
        <<<dim3(1024 / 64, 512 / 64), 256>>>(low, w1, b1, h1, 512, 1024, 8192);
    // L2: (512x1024)@(1024x512) + relu
    sgemm_bias<64, 64, 16, 4, 4, true, false>
        <<<dim3(512 / 64, 512 / 64), 256>>>(h1, w2, b2, h2, 512, 512, 1024);
    // L3: (512x512)@(512x256)
    sgemm_bias<64, 64, 16, 4, 4, false, false>
        <<<dim3(256 / 64, 512 / 64), 256>>>(h2, w3, b3, fe, 512, 256, 512);
    // L4: (512x256)@(256x512) + relu
    sgemm_bias<64, 64, 16, 4, 4, true, false>
        <<<dim3(512 / 64, 512 / 64), 256>>>(fe, w4, b4, d1, 512, 512, 256);
    // L5: (512x512)@(512x1024) + relu, fp16 TILED output [kt][m][16]
    sgemm_bias<64, 64, 16, 4, 4, true, true>
        <<<dim3(1024 / 64, 512 / 64), 256>>>(d1, w5, b5, d2h, 512, 1024, 512);

    // Join, then L6
    cudaStreamWaitEvent(0, ev_join, 0);
    gemm6_fp16<<<dim3(4, NOUTCOL / 128), 256, G6_SMEMB>>>(d2h, w6t, b6, low, out);
}

// round 7
// speedup vs baseline: 1.3535x; 1.2224x over previous
#include <cuda_runtime.h>
#include <cuda_fp16.h>
#include <cstdint>

// ---------------------------------------------------------------------------
// ConstrainedEnhancementModel on GB300 (ptxas target sm_103: no 'a' features).
// R7: gemm6 pipeline deepened to 6 stages / prefetch distance 5 (attacks the
// latency exposure inferred from R4/R5/R6 invariance). pack_w6 fused into the
// L1 launch so gemm6 becomes the 6th kernel launch (ncu -s 5 -c 1 captures it).
// ---------------------------------------------------------------------------

#define NB   512
#define NL   256
#define NF   32
#define NH   4096
#define NOUTCOL (NH * NF)          // 131072
#define LAST_KNOT ((NL - 1) * 16)  // 4080

// Scratch (device globals; allocation-free rule)
__device__ float  g_h1[512 * 1024];
__device__ float  g_h2[512 * 512];
__device__ float  g_fe[512 * 256];
__device__ float  g_d1[512 * 512];
__device__ __half g_d2h[512 * 1024];                // tiled [kt][m][16]
__device__ __half g_w6t[(size_t)NOUTCOL * 1024];    // tiled [nblk][kt][128][16]

// ===========================================================================
// helpers
// ===========================================================================
__device__ __forceinline__ uint32_t smem_u32(const void* p) {
    uint32_t a;
    asm("{ .reg .u64 t; cvta.to.shared.u64 t, %1; cvt.u32.u64 %0, t; }"
        : "=r"(a) : "l"(p));
    return a;
}
__device__ __forceinline__ void cp16_ca(uint32_t dst, const void* src) {
    asm volatile("cp.async.ca.shared.global [%0], [%1], 16;"
                 :: "r"(dst), "l"(src) : "memory");
}
__device__ __forceinline__ void cp16_cg(uint32_t dst, const void* src) {
    asm volatile("cp.async.cg.shared.global [%0], [%1], 16;"
                 :: "r"(dst), "l"(src) : "memory");
}
#define CP_COMMIT() asm volatile("cp.async.commit_group;" ::: "memory")
#define CP_WAIT4()  asm volatile("cp.async.wait_group 4;" ::: "memory")

__device__ __forceinline__ void ldsm_x4(uint32_t& r0, uint32_t& r1,
                                        uint32_t& r2, uint32_t& r3, uint32_t addr) {
    asm volatile("ldmatrix.sync.aligned.m8n8.x4.shared.b16 {%0,%1,%2,%3}, [%4];"
                 : "=r"(r0), "=r"(r1), "=r"(r2), "=r"(r3) : "r"(addr));
}

__device__ __forceinline__ void mma_fp16(float& c0, float& c1, float& c2, float& c3,
                                         uint32_t a0, uint32_t a1, uint32_t a2, uint32_t a3,
                                         uint32_t b0, uint32_t b1) {
    asm volatile(
        "mma.sync.aligned.m16n8k16.row.col.f32.f16.f16.f32 "
        "{%0,%1,%2,%3}, {%4,%5,%6,%7}, {%8,%9}, {%0,%1,%2,%3};"
        : "+f"(c0), "+f"(c1), "+f"(c2), "+f"(c3)
        : "r"(a0), "r"(a1), "r"(a2), "r"(a3), "r"(b0), "r"(b1));
}

// ===========================================================================
// Combined L1 + pack_w6 kernel (heterogeneous 1D grid).
//   blocks [0, 128):       L1 tile: h1 = relu(low @ w1 + b1), 64x64 tile
//   blocks [128, 128+65536): pack w6 fp32 [1024][131072] -> fp16 tile-major
//                           g_w6t[nblk][kt][n128][k16] (4KB contiguous tiles)
// ===========================================================================
__global__ void __launch_bounds__(256)
l1_and_pack(const float* __restrict__ low, const float* __restrict__ w1,
            const float* __restrict__ b1, float* __restrict__ h1,
            const float* __restrict__ w6, __half* __restrict__ w6t)
{
    const int bx  = blockIdx.x;
    const int tid = threadIdx.x;

    if (bx < 128) {
        // ---------------- L1: 64x64x16 tiled SGEMM, M=512,N=1024,K=8192 ----
        constexpr int BM = 64, BN = 64, BK = 16, TM = 4, TN = 4;
        constexpr int THREADS = 256;
        const int N = 1024, K = 8192;
        __shared__ float As[BK][BM + 4];
        __shared__ float Bs[BK][BN];

        const int bn = (bx & 15) * BN;
        const int bm = (bx >> 4) * BM;
        const int tx = tid % (BN / TN);
        const int ty = tid / (BN / TN);

        float acc[TM][TN];
#pragma unroll
        for (int i = 0; i < TM; i++)
#pragma unroll
            for (int j = 0; j < TN; j++) acc[i][j] = 0.0f;

        constexpr int AV = BK / 4, AT = BM * AV;
        constexpr int BV = BN / 4, BT = BK * BV;

        for (int k0 = 0; k0 < K; k0 += BK) {
            for (int i = tid; i < AT; i += THREADS) {
                int r = i / AV, c4 = (i % AV) * 4;
                float4 v = *reinterpret_cast<const float4*>(
                    low + (size_t)(bm + r) * K + k0 + c4);
                As[c4 + 0][r] = v.x; As[c4 + 1][r] = v.y;
                As[c4 + 2][r] = v.z; As[c4 + 3][r] = v.w;
            }
            for (int i = tid; i < BT; i += THREADS) {
                int r = i / BV, c4 = (i % BV) * 4;
                *reinterpret_cast<float4*>(&Bs[r][c4]) =
                    *reinterpret_cast<const float4*>(
                        w1 + (size_t)(k0 + r) * N + bn + c4);
            }
            __syncthreads();
#pragma unroll
            for (int kk = 0; kk < BK; kk++) {
                float ra[TM], rb[TN];
#pragma unroll
                for (int i = 0; i < TM; i += 4)
                    *reinterpret_cast<float4*>(&ra[i]) =
                        *reinterpret_cast<const float4*>(&As[kk][ty * TM + i]);
#pragma unroll
                for (int j = 0; j < TN; j += 4)
                    *reinterpret_cast<float4*>(&rb[j]) =
                        *reinterpret_cast<const float4*>(&Bs[kk][tx * TN + j]);
#pragma unroll
                for (int i = 0; i < TM; i++)
#pragma unroll
                    for (int j = 0; j < TN; j++)
                        acc[i][j] = fmaf(ra[i], rb[j], acc[i][j]);
            }
            __syncthreads();
        }
#pragma unroll
        for (int i = 0; i < TM; i++) {
            int row = bm + ty * TM + i;
#pragma unroll
            for (int j = 0; j < TN; j += 4) {
                int col = bn + tx * TN + j;
                float4 v;
                v.x = fmaxf(acc[i][j + 0] + b1[col + 0], 0.0f);
                v.y = fmaxf(acc[i][j + 1] + b1[col + 1], 0.0f);
                v.z = fmaxf(acc[i][j + 2] + b1[col + 2], 0.0f);
                v.w = fmaxf(acc[i][j + 3] + b1[col + 3], 0.0f);
                *reinterpret_cast<float4*>(h1 + (size_t)row * N + col) = v;
            }
        }
    } else {
        // ---------------- pack_w6 tile ----------------
        __shared__ __half ts[16][136];
        const int pid = bx - 128;
        const int blk = pid >> 6;     // n block 0..1023
        const int kt  = pid & 63;     // k tile 0..63

#pragma unroll
        for (int i = tid; i < 2048; i += 256) {
            const int k = i >> 7, n = i & 127;
            ts[k][n] = __float2half(
                w6[(size_t)(kt * 16 + k) * NOUTCOL + blk * 128 + n]);
        }
        __syncthreads();

        const int n  = tid >> 1;
        const int kh = (tid & 1) * 8;
        __half tmp[8];
#pragma unroll
        for (int j = 0; j < 8; j++) tmp[j] = ts[kh + j][n];
        __half* dst = w6t + ((size_t)(blk * 64 + kt) * 128 + n) * 16 + kh;
        *reinterpret_cast<uint4*>(dst) = *reinterpret_cast<const uint4*>(tmp);
    }
}

// ===========================================================================
// GEMM6 fp16: out = epilogue( d2h @ w6t^T + b6 )
// CTA 128x128, 8 warps (2M x 4N), warp tile 64x32, K-step 16.
// 6-stage cp.async (prefetch distance 5), ldmatrix.x4 frags, pitch 24.
// ===========================================================================
#define G6_STG    6
#define G6_PITCH  24                       // halfs per row (16 data + 8 pad)
#define G6_TILEH  (128 * G6_PITCH)         // 3072 halfs per stage
#define G6_TILEB  (G6_TILEH * 2)           // 6144 bytes per stage
#define G6_NKT    64                       // 1024 / 16
#define G6_SMEMB  (12 * G6_TILEB + 512)    // A(6)+B(6) stages + bias

__global__ void __launch_bounds__(256, 2)
gemm6_fp16(const __half* __restrict__ Ah,   // d2h tiled [64][512][16]
           const __half* __restrict__ Bt,   // w6t tiled [1024][64][128][16]
           const float* __restrict__ bias,  // b6
           const float* __restrict__ low,   // 512 x 256 x 32
           float* __restrict__ out)         // 512 x 4096 x 32
{
    extern __shared__ __half sm[];
    __half* Asm = sm;                        // 6 stages
    __half* Bsm = sm + G6_STG * G6_TILEH;    // 6 stages
    float*  sbias = reinterpret_cast<float*>(sm + 2 * G6_STG * G6_TILEH);

    const int tid  = threadIdx.x;
    const int wid  = tid >> 5;      // 0..7
    const int lane = tid & 31;
    const int g    = lane >> 2;     // 0..7
    const int q    = lane & 3;      // 0..3

    const int bm = blockIdx.x * 128;   // 4 M-blocks fastest -> share w6 in L2
    const int bn = blockIdx.y * 128;

    const int wm = (wid >> 2) * 64;    // 0/64
    const int wn = (wid & 3) * 32;     // 0..96

    if (tid < 128) sbias[tid] = bias[bn + tid];

    // cp.async: contiguous 4KB per stage per operand (256 thr x 16B)
    const __half* aSrc = Ah + (size_t)bm * 16 + tid * 8;                // +8192/kt
    const __half* bSrc = Bt + (size_t)blockIdx.y * 64 * 2048 + tid * 8; // +2048/kt
    const uint32_t aBase = smem_u32(Asm);
    const uint32_t bBase = smem_u32(Bsm);
    const uint32_t aDst = aBase + (tid >> 1) * 48 + (tid & 1) * 16;
    const uint32_t bDst = bBase + (tid >> 1) * 48 + (tid & 1) * 16;

#define G6_LOAD(s, kt)                                         \
    do {                                                       \
        cp16_ca(aDst + (s) * G6_TILEB, aSrc + (kt) * 8192);    \
        cp16_cg(bDst + (s) * G6_TILEB, bSrc + (kt) * 2048);    \
    } while (0)

    G6_LOAD(0, 0); CP_COMMIT();
    G6_LOAD(1, 1); CP_COMMIT();
    G6_LOAD(2, 2); CP_COMMIT();
    G6_LOAD(3, 3); CP_COMMIT();
    G6_LOAD(4, 4); CP_COMMIT();

    // ldmatrix per-thread base addresses (mapping validated in R5/R6)
    const int mi = lane >> 3;      // matrix slot 0..3
    const int r8 = lane & 7;
    const uint32_t aLd = aBase +
        (uint32_t)(((wm + (mi & 1) * 8 + r8) * G6_PITCH + (mi >> 1) * 8) * 2);
    const uint32_t bLd = bBase +
        (uint32_t)(((wn + (mi >> 1) * 8 + r8) * G6_PITCH + (mi & 1) * 8) * 2);

    float acc[4][4][4];
#pragma unroll
    for (int i = 0; i < 4; i++)
#pragma unroll
        for (int j = 0; j < 4; j++)
#pragma unroll
            for (int k = 0; k < 4; k++) acc[i][j][k] = 0.0f;

    int s  = 0;                 // stage being consumed
    int sl = G6_STG - 1;        // stage being loaded (kt+5)
    for (int kt = 0; kt < G6_NKT; kt++) {
        CP_WAIT4();
        __syncthreads();
        if (kt + 5 < G6_NKT) {
            G6_LOAD(sl, kt + 5);
        }
        CP_COMMIT();            // commit (possibly empty) keeps group counting

        const uint32_t so = (uint32_t)s * G6_TILEB;

        uint32_t bf[4][2];
#pragma unroll
        for (int p = 0; p < 2; p++)    // 16 n-rows per ldsm.x4
            ldsm_x4(bf[2 * p][0], bf[2 * p][1],
                    bf[2 * p + 1][0], bf[2 * p + 1][1],
                    bLd + p * (16 * G6_PITCH * 2) + so);

#pragma unroll
        for (int mt = 0; mt < 4; mt++) {
            uint32_t a0, a1, a2, a3;
            ldsm_x4(a0, a1, a2, a3, aLd + mt * (16 * G6_PITCH * 2) + so);
#pragma unroll
            for (int nt = 0; nt < 4; nt++)
                mma_fp16(acc[mt][nt][0], acc[mt][nt][1],
                         acc[mt][nt][2], acc[mt][nt][3],
                         a0, a1, a2, a3, bf[nt][0], bf[nt][1]);
        }

        s  = (s  + 1 == G6_STG) ? 0 : s  + 1;
        sl = (sl + 1 == G6_STG) ? 0 : sl + 1;
    }

    // ---- fused epilogue (warp-uniform t) ----
    const int t   = (bn + wn) >> 5;
    const int rem = t & 15;
    const int seg = t >> 4;
    const bool knot  = (rem == 0);
    const bool inseg = (!knot) && (t < LAST_KNOT);
    const float alpha = (float)rem * 0.0625f;
    const int segB = (seg < NL - 1) ? seg + 1 : NL - 1;

#pragma unroll
    for (int mt = 0; mt < 4; mt++) {
#pragma unroll
        for (int h = 0; h < 2; h++) {
            const int r = bm + wm + mt * 16 + g + h * 8;
            const float* lowr = low + (size_t)r * (NL * NF);
            float* outr = out + (size_t)r * NOUTCOL + bn + wn;
#pragma unroll
            for (int nt = 0; nt < 4; nt++) {
                const int f = nt * 8 + 2 * q;
                float dec0 = acc[mt][nt][2 * h]     + sbias[wn + f];
                float dec1 = acc[mt][nt][2 * h + 1] + sbias[wn + f + 1];
                float2 la = *reinterpret_cast<const float2*>(lowr + seg  * NF + f);
                float2 lb = *reinterpret_cast<const float2*>(lowr + segB * NF + f);
                float lin0 = (1.0f - alpha) * la.x + alpha * lb.x;
                float lin1 = (1.0f - alpha) * la.y + alpha * lb.y;
                float r0 = knot ? la.x : (inseg ? 0.8f * lin0 + 0.2f * dec0 : dec0);
                float r1 = knot ? la.y : (inseg ? 0.8f * lin1 + 0.2f * dec1 : dec1);
                *reinterpret_cast<float2*>(outr + f) = make_float2(r0, r1);
            }
        }
    }
#undef G6_LOAD
}

// ===========================================================================
// Small-layer SIMT SGEMM; TILEDH=true stores fp16 tiled [col/16][row][16]
// ===========================================================================
template <int BM, int BN, int BK, int TM, int TN, bool RELU, bool TILEDH>
__global__ __launch_bounds__((BM / TM) * (BN / TN))
void sgemm_bias(const float* __restrict__ A, const float* __restrict__ Bm,
                const float* __restrict__ bias, void* __restrict__ Cv,
                int M, int N, int K)
{
    constexpr int THREADS = (BM / TM) * (BN / TN);
    __shared__ float As[BK][BM + 4];
    __shared__ float Bs[BK][BN];

    const int tid = threadIdx.x;
    const int bn  = blockIdx.x * BN;
    const int bm  = blockIdx.y * BM;
    const int tx  = tid % (BN / TN);
    const int ty  = tid / (BN / TN);

    float acc[TM][TN];
#pragma unroll
    for (int i = 0; i < TM; i++)
#pragma unroll
        for (int j = 0; j < TN; j++) acc[i][j] = 0.0f;

    constexpr int AV = BK / 4, AT = BM * AV;
    constexpr int BV = BN / 4, BT = BK * BV;

    for (int k0 = 0; k0 < K; k0 += BK) {
        for (int i = tid; i < AT; i += THREADS) {
            int r = i / AV, c4 = (i % AV) * 4;
            float4 v = *reinterpret_cast<const float4*>(
                A + (size_t)(bm + r) * K + k0 + c4);
            As[c4 + 0][r] = v.x; As[c4 + 1][r] = v.y;
            As[c4 + 2][r] = v.z; As[c4 + 3][r] = v.w;
        }
        for (int i = tid; i < BT; i += THREADS) {
            int r = i / BV, c4 = (i % BV) * 4;
            *reinterpret_cast<float4*>(&Bs[r][c4]) =
                *reinterpret_cast<const float4*>(
                    Bm + (size_t)(k0 + r) * N + bn + c4);
        }
        __syncthreads();

#pragma unroll
        for (int kk = 0; kk < BK; kk++) {
            float ra[TM], rb[TN];
#pragma unroll
            for (int i = 0; i < TM; i += 4)
                *reinterpret_cast<float4*>(&ra[i]) =
                    *reinterpret_cast<const float4*>(&As[kk][ty * TM + i]);
#pragma unroll
            for (int j = 0; j < TN; j += 4)
                *reinterpret_cast<float4*>(&rb[j]) =
                    *reinterpret_cast<const float4*>(&Bs[kk][tx * TN + j]);
#pragma unroll
            for (int i = 0; i < TM; i++)
#pragma unroll
                for (int j = 0; j < TN; j++)
                    acc[i][j] = fmaf(ra[i], rb[j], acc[i][j]);
        }
        __syncthreads();
    }

#pragma unroll
    for (int i = 0; i < TM; i++) {
        int row = bm + ty * TM + i;
#pragma unroll
        for (int j = 0; j < TN; j += 4) {
            int col = bn + tx * TN + j;
            float4 v;
            v.x = acc[i][j + 0] + bias[col + 0];
            v.y = acc[i][j + 1] + bias[col + 1];
            v.z = acc[i][j + 2] + bias[col + 2];
            v.w = acc[i][j + 3] + bias[col + 3];
            if (RELU) {
                v.x = fmaxf(v.x, 0.0f);
                v.y = fmaxf(v.y, 0.0f);
                v.z = fmaxf(v.z, 0.0f);
                v.w = fmaxf(v.w, 0.0f);
            }
            if (TILEDH) {
                __half* C = (__half*)Cv;
                __half* p = C + ((size_t)(col >> 4) * M + row) * 16 + (col & 15);
                __half2 h0 = __floats2half2_rn(v.x, v.y);
                __half2 h1 = __floats2half2_rn(v.z, v.w);
                *reinterpret_cast<__half2*>(p)     = h0;
                *reinterpret_cast<__half2*>(p + 2) = h1;
            } else {
                float* C = (float*)Cv;
                *reinterpret_cast<float4*>(C + (size_t)row * N + col) = v;
            }
        }
    }
}

// ---------------------------------------------------------------------------
extern "C" void kernel_launch(void* const* d_in, const int* in_sizes, int n_in,
                              void* d_out, int out_size)
{
    const float* low = (const float*)d_in[0];
    const float* w1  = (const float*)d_in[1];
    const float* b1  = (const float*)d_in[2];
    const float* w2  = (const float*)d_in[3];
    const float* b2  = (const float*)d_in[4];
    const float* w3  = (const float*)d_in[5];
    const float* b3  = (const float*)d_in[6];
    const float* w4  = (const float*)d_in[7];
    const float* b4  = (const float*)d_in[8];
    const float* w5  = (const float*)d_in[9];
    const float* b5  = (const float*)d_in[10];
    const float* w6  = (const float*)d_in[11];
    const float* b6  = (const float*)d_in[12];
    float* out = (float*)d_out;

    float  *h1, *h2, *fe, *d1;
    __half *d2h, *w6t;
    cudaGetSymbolAddress((void**)&h1,  g_h1);
    cudaGetSymbolAddress((void**)&h2,  g_h2);
    cudaGetSymbolAddress((void**)&fe,  g_fe);
    cudaGetSymbolAddress((void**)&d1,  g_d1);
    cudaGetSymbolAddress((void**)&d2h, g_d2h);
    cudaGetSymbolAddress((void**)&w6t, g_w6t);

    cudaFuncSetAttribute(gemm6_fp16,
                         cudaFuncAttributeMaxDynamicSharedMemorySize, G6_SMEMB);

    // Launch 1: L1 (blocks 0..127) + pack_w6 (blocks 128..65663)
    l1_and_pack<<<128 + 1024 * 64, 256>>>(low, w1, b1, h1, w6, w6t);
    // Launch 2: L2 (512x1024)@(1024x512) + relu
    sgemm_bias<64, 64, 16, 4, 4, true, false>
        <<<dim3(512 / 64, 512 / 64), 256>>>(h1, w2, b2, h2, 512, 512, 1024);
    // Launch 3: L3 (512x512)@(512x256)
    sgemm_bias<64, 64, 16, 4, 4, false, false>
        <<<dim3(256 / 64, 512 / 64), 256>>>(h2, w3, b3, fe, 512, 256, 512);
    // Launch 4: L4 (512x256)@(256x512) + relu
    sgemm_bias<64, 64, 16, 4, 4, true, false>
        <<<dim3(512 / 64, 512 / 64), 256>>>(fe, w4, b4, d1, 512, 512, 256);
    // Launch 5: L5 (512x512)@(512x1024) + relu, fp16 TILED output [kt][m][16]
    sgemm_bias<64, 64, 16, 4, 4, true, true>
        <<<dim3(1024 / 64, 512 / 64), 256>>>(d1, w5, b5, d2h, 512, 1024, 512);
    // Launch 6: GEMM6 (captured by ncu -s 5 -c 1)
    gemm6_fp16<<<dim3(4, NOUTCOL / 128), 256, G6_SMEMB>>>(d2h, w6t, b6, low, out);
}